// round 3
// baseline (speedup 1.0000x reference)
#include <cuda_runtime.h>
#include <math.h>

// ---------------------------------------------------------------------------
// Differentiable JPEG (quality 80) forward pass, fused single kernel.
// Tile = 16x16 pixels = 4 Y blocks + 1 Cb + 1 Cr (chroma 2x2-downsampled).
// One CTA (64 threads) per tile; each thread owns a 2x2 pixel quad.
// DCT basis baked as FFMA immediates; inter-stage transposes via shfl.xor
// butterflies inside each 8-lane octet (no shared round trips between the
// x-pass, y-pass+quant, and inverse x-pass).
// ---------------------------------------------------------------------------

#define IMG_H 512
#define IMG_W 512

__constant__ float c_YTAB[64] = {
    16,11,10,16,24,40,51,61,  12,12,14,19,26,58,60,55,
    14,13,16,24,40,57,69,56,  14,17,22,29,51,87,80,62,
    18,22,37,56,68,109,103,77, 24,35,55,64,81,104,113,92,
    49,64,78,87,103,121,120,101, 72,92,95,98,112,100,103,99};
__constant__ float c_CTAB[64] = {
    17,18,24,47,99,99,99,99,  18,21,26,66,99,99,99,99,
    24,26,56,99,99,99,99,99,  47,66,99,99,99,99,99,99,
    99,99,99,99,99,99,99,99,  99,99,99,99,99,99,99,99,
    99,99,99,99,99,99,99,99,  99,99,99,99,99,99,99,99};

// cos(k*pi/16)
#define C1 0.980785280403230449f
#define C2 0.923879532511286756f
#define C3 0.831469612302545237f
#define C4 0.707106781186547524f
#define C5 0.555570233019602225f
#define C6 0.382683432365089772f
#define C7 0.195090322016128268f

// 8x8 transpose across an 8-lane octet: lane l holds r[0..7] (= row l);
// afterwards lane l holds column l. Butterfly: stage m swaps bit m between
// the lane index and the register index. 4 shfl per stage, 3 stages.
__device__ __forceinline__ void transpose8(float r[8], int lane) {
    #pragma unroll
    for (int m = 1; m < 8; m <<= 1) {
        const bool hi = (lane & m) != 0;
        #pragma unroll
        for (int i = 0; i < 8; i++) {
            if ((i & m) == 0) {
                float send = hi ? r[i] : r[i + m];
                float recv = __shfl_xor_sync(0xFFFFFFFFu, send, m);
                if (hi) r[i] = recv; else r[i + m] = recv;
            }
        }
    }
}

__global__ void __launch_bounds__(64)
jpeg_tile_kernel(const float* __restrict__ img, float* __restrict__ out) {
    // CT[x][u] = cos((2x+1)*u*pi/16) — constant-folded to FFMA immediates.
    constexpr float CT[8][8] = {
        {1.f,  C1,  C2,  C3,  C4,  C5,  C6,  C7},
        {1.f,  C3,  C6, -C7, -C4, -C1, -C2, -C5},
        {1.f,  C5, -C6, -C1, -C4,  C7,  C2,  C3},
        {1.f,  C7, -C2, -C5,  C4,  C3, -C6, -C1},
        {1.f, -C7, -C2,  C5,  C4, -C3, -C6,  C1},
        {1.f, -C5, -C6,  C1, -C4, -C7,  C2, -C3},
        {1.f, -C3,  C6,  C7, -C4,  C1, -C2,  C5},
        {1.f, -C1,  C2, -C3,  C4, -C5,  C6, -C7}};

    __shared__ float sAq[2][64];    // (ALPHA*0.25)/q
    __shared__ float sBq[2][64];    // (ALPHA*0.25)*q
    __shared__ float s1[6][8][9];   // pixel-domain staging (Y0..3, Cb, Cr)
    __shared__ float s2[6][8][9];   // reconstructed pixel-domain

    const int t = threadIdx.x;

    // Build quant-scale tables (t indexes [u][v] flattened)
    {
        int u = t >> 3, v = t & 7;
        float au = (u == 0) ? 0.70710678118654752f : 1.f;
        float av = (v == 0) ? 0.70710678118654752f : 1.f;
        float S = au * av * 0.25f;
        float qy = c_YTAB[t] * 0.4f;   // QUALITY=80 -> FACTOR=0.4
        float qc = c_CTAB[t] * 0.4f;
        sAq[0][t] = S / qy;  sBq[0][t] = S * qy;
        sAq[1][t] = S / qc;  sBq[1][t] = S * qc;
    }

    const int tile = blockIdx.x;
    const int tx   = tile & 31;
    const int ty   = (tile >> 5) & 31;
    const int bimg = tile >> 10;

    const int qx = t & 7, qy = t >> 3;        // quad coords in tile
    const int px = tx * 16 + qx * 2;
    const int py = ty * 16 + qy * 2;

    const size_t plane = (size_t)IMG_H * IMG_W;
    const float* pR = img + (size_t)bimg * 3 * plane + (size_t)py * IMG_W + px;
    const float* pG = pR + plane;
    const float* pB = pR + 2 * plane;

    float2 r0 = *(const float2*)pR;
    float2 r1 = *(const float2*)(pR + IMG_W);
    float2 g0 = *(const float2*)pG;
    float2 g1 = *(const float2*)(pG + IMG_W);
    float2 b0 = *(const float2*)pB;
    float2 b1 = *(const float2*)(pB + IMG_W);

    float Rq[2][2] = {{r0.x, r0.y}, {r1.x, r1.y}};
    float Gq[2][2] = {{g0.x, g0.y}, {g1.x, g1.y}};
    float Bq[2][2] = {{b0.x, b0.y}, {b1.x, b1.y}};

    float cbs = 0.f, crs = 0.f;
    #pragma unroll
    for (int dr = 0; dr < 2; dr++) {
        #pragma unroll
        for (int dc = 0; dc < 2; dc++) {
            float r = Rq[dr][dc] * 255.f;
            float g = Gq[dr][dc] * 255.f;
            float b = Bq[dr][dc] * 255.f;
            float y = 0.299f * r + 0.587f * g + 0.114f * b - 128.f;  // -128 folded
            cbs += -0.168736f * r - 0.331264f * g + 0.5f      * b;   // shifts cancel
            crs +=  0.5f      * r - 0.418688f * g - 0.081312f * b;
            int prow = qy * 2 + dr, pcol = qx * 2 + dc;
            int blk = ((prow >> 3) << 1) + (pcol >> 3);
            s1[blk][prow & 7][pcol & 7] = y;
        }
    }
    s1[4][qy][qx] = cbs * 0.25f;
    s1[5][qy][qx] = crs * 0.25f;
    __syncthreads();

    // ---- Fused DCT -> quant(diff_round) -> IDCT, one straight-line region.
    // 48 real tasks (6 blocks x 8 lanes); lanes 48..63 duplicate blocks 0,1
    // (identical inputs -> bitwise-identical redundant writes) to keep warps
    // convergent for the shuffles.
    {
        int blk = t >> 3; if (blk >= 6) blk -= 6;
        const int j  = t & 7;                 // column within block / lane in octet
        const int ti = (blk < 4) ? 0 : 1;

        // Stage A: 1-D DCT along x on column j. a[u] = sum_x CT[x][u]*col[x]
        float in[8];
        #pragma unroll
        for (int x = 0; x < 8; x++) in[x] = s1[blk][x][j];
        float a[8];
        #pragma unroll
        for (int u = 0; u < 8; u++) {
            float acc = 0.f;
            #pragma unroll
            for (int x = 0; x < 8; x++) acc += in[x] * CT[x][u];
            a[u] = acc;
        }

        // Transpose: lane j now holds row u=j of the stage-A result over y.
        transpose8(a, j);
        const int u = j;

        // Quant rows (contiguous 32B -> float4 loads)
        const float4 qa0 = *(const float4*)&sAq[ti][u * 8];
        const float4 qa1 = *(const float4*)&sAq[ti][u * 8 + 4];
        const float4 qb0 = *(const float4*)&sBq[ti][u * 8];
        const float4 qb1 = *(const float4*)&sBq[ti][u * 8 + 4];
        const float Aq[8] = {qa0.x, qa0.y, qa0.z, qa0.w, qa1.x, qa1.y, qa1.z, qa1.w};
        const float Bq2[8] = {qb0.x, qb0.y, qb0.z, qb0.w, qb1.x, qb1.y, qb1.z, qb1.w};

        // Stage B: DCT along y, diff_round quant, IDCT along y.
        float h[8];
        #pragma unroll
        for (int v = 0; v < 8; v++) {
            float raw = 0.f;
            #pragma unroll
            for (int y = 0; y < 8; y++) raw += a[y] * CT[y][v];
            float c = raw * Aq[v];
            float r = rintf(c);               // round-half-even == jnp.round
            float d = c - r;
            h[v] = (r + d * d * d) * Bq2[v];
        }
        float g[8];
        #pragma unroll
        for (int y = 0; y < 8; y++) {
            float acc = 0.f;
            #pragma unroll
            for (int v = 0; v < 8; v++) acc += h[v] * CT[y][v];
            g[y] = acc;
        }

        // Transpose back: lane j holds column j over u.
        transpose8(g, j);

        // Stage C: IDCT along x; +128 for Y (chroma shifts cancel).
        const float add = (blk < 4) ? 128.f : 0.f;
        #pragma unroll
        for (int x = 0; x < 8; x++) {
            float acc = 0.f;
            #pragma unroll
            for (int uu = 0; uu < 8; uu++) acc += g[uu] * CT[x][uu];
            s2[blk][x][j] = acc + add;
        }
    }
    __syncthreads();

    // ---- Writeback: upsample chroma, YCbCr->RGB, clip.
    float cb = s2[4][qy][qx];
    float cr = s2[5][qy][qx];

    float* qR = out + (size_t)bimg * 3 * plane + (size_t)py * IMG_W + px;
    float* qG = qR + plane;
    float* qB = qR + 2 * plane;

    #pragma unroll
    for (int dr = 0; dr < 2; dr++) {
        float2 ro, go, bo;
        #pragma unroll
        for (int dc = 0; dc < 2; dc++) {
            int prow = qy * 2 + dr, pcol = qx * 2 + dc;
            int blk = ((prow >> 3) << 1) + (pcol >> 3);
            float y = s2[blk][prow & 7][pcol & 7];
            float Rv = y + 1.402f * cr;
            float Gv = y - 0.344136f * cb - 0.714136f * cr;
            float Bv = y + 1.772f * cb;
            Rv = fminf(fmaxf(Rv, 0.f), 255.f) * (1.f / 255.f);
            Gv = fminf(fmaxf(Gv, 0.f), 255.f) * (1.f / 255.f);
            Bv = fminf(fmaxf(Bv, 0.f), 255.f) * (1.f / 255.f);
            if (dc == 0) { ro.x = Rv; go.x = Gv; bo.x = Bv; }
            else         { ro.y = Rv; go.y = Gv; bo.y = Bv; }
        }
        *(float2*)(qR + dr * IMG_W) = ro;
        *(float2*)(qG + dr * IMG_W) = go;
        *(float2*)(qB + dr * IMG_W) = bo;
    }
}

extern "C" void kernel_launch(void* const* d_in, const int* in_sizes, int n_in,
                              void* d_out, int out_size) {
    const float* img = (const float*)d_in[0];
    float* out = (float*)d_out;
    int batch = in_sizes[0] / (3 * IMG_H * IMG_W);   // 32
    int tiles = batch * (IMG_H / 16) * (IMG_W / 16); // 32768

    jpeg_tile_kernel<<<tiles, 64>>>(img, out);
}

// round 4
// speedup vs baseline: 1.1607x; 1.1607x over previous
#include <cuda_runtime.h>
#include <math.h>

// ---------------------------------------------------------------------------
// Differentiable JPEG (quality 80) forward pass, fused single kernel.
// Tile = 32x16 pixels = 8 Y blocks + 2 Cb + 2 Cr (chroma 2x2-downsampled).
// One CTA (128 threads) per tile; each thread owns a 2x2 pixel quad.
// 32-px tile width -> every global float2 access is a full 128-B wavefront
// per half-warp. DCT basis baked as FFMA immediates; transposes via shared
// (conflict-free [8][9] layout).
// ---------------------------------------------------------------------------

#define IMG_H 512
#define IMG_W 512

__constant__ float c_YTAB[64] = {
    16,11,10,16,24,40,51,61,  12,12,14,19,26,58,60,55,
    14,13,16,24,40,57,69,56,  14,17,22,29,51,87,80,62,
    18,22,37,56,68,109,103,77, 24,35,55,64,81,104,113,92,
    49,64,78,87,103,121,120,101, 72,92,95,98,112,100,103,99};
__constant__ float c_CTAB[64] = {
    17,18,24,47,99,99,99,99,  18,21,26,66,99,99,99,99,
    24,26,56,99,99,99,99,99,  47,66,99,99,99,99,99,99,
    99,99,99,99,99,99,99,99,  99,99,99,99,99,99,99,99,
    99,99,99,99,99,99,99,99,  99,99,99,99,99,99,99,99};

// cos(k*pi/16)
#define C1 0.980785280403230449f
#define C2 0.923879532511286756f
#define C3 0.831469612302545237f
#define C4 0.707106781186547524f
#define C5 0.555570233019602225f
#define C6 0.382683432365089772f
#define C7 0.195090322016128268f

__global__ void __launch_bounds__(128)
jpeg_tile_kernel(const float* __restrict__ img, float* __restrict__ out) {
    // CT[x][u] = cos((2x+1)*u*pi/16) — constant-folded to FFMA immediates.
    constexpr float CT[8][8] = {
        {1.f,  C1,  C2,  C3,  C4,  C5,  C6,  C7},
        {1.f,  C3,  C6, -C7, -C4, -C1, -C2, -C5},
        {1.f,  C5, -C6, -C1, -C4,  C7,  C2,  C3},
        {1.f,  C7, -C2, -C5,  C4,  C3, -C6, -C1},
        {1.f, -C7, -C2,  C5,  C4, -C3, -C6,  C1},
        {1.f, -C5, -C6,  C1, -C4, -C7,  C2, -C3},
        {1.f, -C3,  C6,  C7, -C4,  C1, -C2,  C5},
        {1.f, -C1,  C2, -C3,  C4, -C5,  C6, -C7}};

    __shared__ float sAq[2][64];     // (ALPHA*0.25)/q
    __shared__ float sBq[2][64];     // (ALPHA*0.25)*q
    __shared__ float s1[12][8][9];   // blocks 0..7 = Y, 8..9 = Cb, 10..11 = Cr
    __shared__ float s2[12][8][9];

    const int t = threadIdx.x;

    // Build quant-scale tables (threads 0..63; t indexes [u][v] flattened)
    if (t < 64) {
        int u = t >> 3, v = t & 7;
        float au = (u == 0) ? 0.70710678118654752f : 1.f;
        float av = (v == 0) ? 0.70710678118654752f : 1.f;
        float S = au * av * 0.25f;
        float qy = c_YTAB[t] * 0.4f;   // QUALITY=80 -> FACTOR=0.4
        float qc = c_CTAB[t] * 0.4f;
        sAq[0][t] = S / qy;  sBq[0][t] = S * qy;
        sAq[1][t] = S / qc;  sBq[1][t] = S * qc;
    }

    const int tile = blockIdx.x;
    const int tx   = tile & 15;          // 16 tiles across (32 px each)
    const int ty   = (tile >> 4) & 31;   // 32 tiles down (16 px each)
    const int bimg = tile >> 9;

    const int qx = t & 15, qy = t >> 4;  // quad coords: 16 x 8 quads
    const int px = tx * 32 + qx * 2;
    const int py = ty * 16 + qy * 2;

    const size_t plane = (size_t)IMG_H * IMG_W;
    const float* pR = img + (size_t)bimg * 3 * plane + (size_t)py * IMG_W + px;
    const float* pG = pR + plane;
    const float* pB = pR + 2 * plane;

    float2 r0 = *(const float2*)pR;
    float2 r1 = *(const float2*)(pR + IMG_W);
    float2 g0 = *(const float2*)pG;
    float2 g1 = *(const float2*)(pG + IMG_W);
    float2 b0 = *(const float2*)pB;
    float2 b1 = *(const float2*)(pB + IMG_W);

    float Rq[2][2] = {{r0.x, r0.y}, {r1.x, r1.y}};
    float Gq[2][2] = {{g0.x, g0.y}, {g1.x, g1.y}};
    float Bq[2][2] = {{b0.x, b0.y}, {b1.x, b1.y}};

    float cbs = 0.f, crs = 0.f;
    #pragma unroll
    for (int dr = 0; dr < 2; dr++) {
        #pragma unroll
        for (int dc = 0; dc < 2; dc++) {
            float r = Rq[dr][dc] * 255.f;
            float g = Gq[dr][dc] * 255.f;
            float b = Bq[dr][dc] * 255.f;
            float y = 0.299f * r + 0.587f * g + 0.114f * b - 128.f;  // -128 folded
            cbs += -0.168736f * r - 0.331264f * g + 0.5f      * b;   // shifts cancel
            crs +=  0.5f      * r - 0.418688f * g - 0.081312f * b;
            int prow = qy * 2 + dr, pcol = qx * 2 + dc;
            int blk = ((prow >> 3) << 2) + (pcol >> 3);   // 4 across x 2 down
            s1[blk][prow & 7][pcol & 7] = y;
        }
    }
    s1[8  + (qx >> 3)][qy][qx & 7] = cbs * 0.25f;
    s1[10 + (qx >> 3)][qy][qx & 7] = crs * 0.25f;
    __syncthreads();

    // ---- Stage A: 1-D DCT along x: s2[b][u][j] = sum_x CT[x][u]*s1[b][x][j]
    if (t < 96) {
        int blk = t >> 3, j = t & 7;
        float in[8];
        #pragma unroll
        for (int x = 0; x < 8; x++) in[x] = s1[blk][x][j];
        #pragma unroll
        for (int u = 0; u < 8; u++) {
            float acc = 0.f;
            #pragma unroll
            for (int x = 0; x < 8; x++) acc += in[x] * CT[x][u];
            s2[blk][u][j] = acc;
        }
    }
    __syncthreads();

    // ---- Stage B: DCT along y, diff_round quant, IDCT along y.
    if (t < 96) {
        int blk = t >> 3, u = t & 7;
        int ti = (blk < 8) ? 0 : 1;
        float row[8];
        #pragma unroll
        for (int y = 0; y < 8; y++) row[y] = s2[blk][u][y];

        const float4 qa0 = *(const float4*)&sAq[ti][u * 8];
        const float4 qa1 = *(const float4*)&sAq[ti][u * 8 + 4];
        const float4 qb0 = *(const float4*)&sBq[ti][u * 8];
        const float4 qb1 = *(const float4*)&sBq[ti][u * 8 + 4];
        const float Aq[8]  = {qa0.x, qa0.y, qa0.z, qa0.w, qa1.x, qa1.y, qa1.z, qa1.w};
        const float Bq2[8] = {qb0.x, qb0.y, qb0.z, qb0.w, qb1.x, qb1.y, qb1.z, qb1.w};

        float h[8];
        #pragma unroll
        for (int v = 0; v < 8; v++) {
            float raw = 0.f;
            #pragma unroll
            for (int y = 0; y < 8; y++) raw += row[y] * CT[y][v];
            float c = raw * Aq[v];
            float r = rintf(c);               // round-half-even == jnp.round
            float d = c - r;
            h[v] = (r + d * d * d) * Bq2[v];
        }
        #pragma unroll
        for (int y = 0; y < 8; y++) {
            float acc = 0.f;
            #pragma unroll
            for (int v = 0; v < 8; v++) acc += h[v] * CT[y][v];
            s1[blk][u][y] = acc;
        }
    }
    __syncthreads();

    // ---- Stage C: IDCT along x: s2[b][x][j] = sum_u CT[x][u]*s1[b][u][j]
    if (t < 96) {
        int blk = t >> 3, j = t & 7;
        float in[8];
        #pragma unroll
        for (int u = 0; u < 8; u++) in[u] = s1[blk][u][j];
        float add = (blk < 8) ? 128.f : 0.f;   // chroma +128/-128 cancels
        #pragma unroll
        for (int x = 0; x < 8; x++) {
            float acc = 0.f;
            #pragma unroll
            for (int u = 0; u < 8; u++) acc += in[u] * CT[x][u];
            s2[blk][x][j] = acc + add;
        }
    }
    __syncthreads();

    // ---- Writeback: upsample chroma, YCbCr->RGB, clip.
    float cb = s2[8  + (qx >> 3)][qy][qx & 7];
    float cr = s2[10 + (qx >> 3)][qy][qx & 7];

    float* qR = out + (size_t)bimg * 3 * plane + (size_t)py * IMG_W + px;
    float* qG = qR + plane;
    float* qB = qR + 2 * plane;

    #pragma unroll
    for (int dr = 0; dr < 2; dr++) {
        float2 ro, go, bo;
        #pragma unroll
        for (int dc = 0; dc < 2; dc++) {
            int prow = qy * 2 + dr, pcol = qx * 2 + dc;
            int blk = ((prow >> 3) << 2) + (pcol >> 3);
            float y = s2[blk][prow & 7][pcol & 7];
            float Rv = y + 1.402f * cr;
            float Gv = y - 0.344136f * cb - 0.714136f * cr;
            float Bv = y + 1.772f * cb;
            Rv = fminf(fmaxf(Rv, 0.f), 255.f) * (1.f / 255.f);
            Gv = fminf(fmaxf(Gv, 0.f), 255.f) * (1.f / 255.f);
            Bv = fminf(fmaxf(Bv, 0.f), 255.f) * (1.f / 255.f);
            if (dc == 0) { ro.x = Rv; go.x = Gv; bo.x = Bv; }
            else         { ro.y = Rv; go.y = Gv; bo.y = Bv; }
        }
        *(float2*)(qR + dr * IMG_W) = ro;
        *(float2*)(qG + dr * IMG_W) = go;
        *(float2*)(qB + dr * IMG_W) = bo;
    }
}

extern "C" void kernel_launch(void* const* d_in, const int* in_sizes, int n_in,
                              void* d_out, int out_size) {
    const float* img = (const float*)d_in[0];
    float* out = (float*)d_out;
    int batch = in_sizes[0] / (3 * IMG_H * IMG_W);             // 32
    int tiles = batch * (IMG_H / 16) * (IMG_W / 32);           // 16384
    jpeg_tile_kernel<<<tiles, 128>>>(img, out);
}

// round 5
// speedup vs baseline: 1.3697x; 1.1801x over previous
#include <cuda_runtime.h>
#include <math.h>

// ---------------------------------------------------------------------------
// Differentiable JPEG (quality 80) forward pass, fused single kernel.
// Tile = 32x16 pixels = 8 Y blocks + 2 Cb + 2 Cr (chroma 2x2-downsampled).
// One CTA (128 threads) per tile; each thread owns a 2x2 pixel quad.
// DCT basis baked as immediates; even/odd butterfly halves the FMA count.
// Shared [8][9] layout keeps every stage access bank-conflict-free.
// ---------------------------------------------------------------------------

#define IMG_H 512
#define IMG_W 512

__constant__ float c_YTAB[64] = {
    16,11,10,16,24,40,51,61,  12,12,14,19,26,58,60,55,
    14,13,16,24,40,57,69,56,  14,17,22,29,51,87,80,62,
    18,22,37,56,68,109,103,77, 24,35,55,64,81,104,113,92,
    49,64,78,87,103,121,120,101, 72,92,95,98,112,100,103,99};
__constant__ float c_CTAB[64] = {
    17,18,24,47,99,99,99,99,  18,21,26,66,99,99,99,99,
    24,26,56,99,99,99,99,99,  47,66,99,99,99,99,99,99,
    99,99,99,99,99,99,99,99,  99,99,99,99,99,99,99,99,
    99,99,99,99,99,99,99,99,  99,99,99,99,99,99,99,99};

// cos(k*pi/16)
#define C1 0.980785280403230449f
#define C2 0.923879532511286756f
#define C3 0.831469612302545237f
#define C4 0.707106781186547524f
#define C5 0.555570233019602225f
#define C6 0.382683432365089772f
#define C7 0.195090322016128268f

// Forward 8-pt DCT-II basis contraction: a[u] = sum_x in[x]*CT[x][u],
// via even/odd butterfly (CT[7-x][u] = (-1)^u CT[x][u]).
__device__ __forceinline__ void dct8_fwd(const float in[8], float a[8]) {
    float s0 = in[0] + in[7], s1 = in[1] + in[6];
    float s2 = in[2] + in[5], s3 = in[3] + in[4];
    float d0 = in[0] - in[7], d1 = in[1] - in[6];
    float d2 = in[2] - in[5], d3 = in[3] - in[4];
    a[0] = (s0 + s3) + (s1 + s2);
    a[2] = C2 * s0 + C6 * s1 - C6 * s2 - C2 * s3;
    a[4] = C4 * ((s0 + s3) - (s1 + s2));
    a[6] = C6 * s0 - C2 * s1 + C2 * s2 - C6 * s3;
    a[1] = C1 * d0 + C3 * d1 + C5 * d2 + C7 * d3;
    a[3] = C3 * d0 - C7 * d1 - C1 * d2 - C5 * d3;
    a[5] = C5 * d0 - C1 * d1 + C7 * d2 + C3 * d3;
    a[7] = C7 * d0 - C5 * d1 + C3 * d2 - C1 * d3;
}

// Inverse contraction: p[x] = sum_u h[u]*CT[x][u], via even/odd halves.
__device__ __forceinline__ void dct8_inv(const float h[8], float p[8]) {
    float e0 = h[0] + C2 * h[2] + C4 * h[4] + C6 * h[6];
    float e1 = h[0] + C6 * h[2] - C4 * h[4] - C2 * h[6];
    float e2 = h[0] - C6 * h[2] - C4 * h[4] + C2 * h[6];
    float e3 = h[0] - C2 * h[2] + C4 * h[4] - C6 * h[6];
    float o0 = C1 * h[1] + C3 * h[3] + C5 * h[5] + C7 * h[7];
    float o1 = C3 * h[1] - C7 * h[3] - C1 * h[5] - C5 * h[7];
    float o2 = C5 * h[1] - C1 * h[3] + C7 * h[5] + C3 * h[7];
    float o3 = C7 * h[1] - C5 * h[3] + C3 * h[5] - C1 * h[7];
    p[0] = e0 + o0;  p[7] = e0 - o0;
    p[1] = e1 + o1;  p[6] = e1 - o1;
    p[2] = e2 + o2;  p[5] = e2 - o2;
    p[3] = e3 + o3;  p[4] = e3 - o3;
}

__global__ void __launch_bounds__(128)
jpeg_tile_kernel(const float* __restrict__ img, float* __restrict__ out) {
    __shared__ float sAq[2][64];     // (ALPHA*0.25)/q
    __shared__ float sBq[2][64];     // (ALPHA*0.25)*q
    __shared__ float s1[12][8][9];   // blocks 0..7 = Y, 8..9 = Cb, 10..11 = Cr
    __shared__ float s2[12][8][9];

    const int t = threadIdx.x;

    // Build quant-scale tables (threads 0..63; t indexes [u][v] flattened)
    if (t < 64) {
        int u = t >> 3, v = t & 7;
        float au = (u == 0) ? 0.70710678118654752f : 1.f;
        float av = (v == 0) ? 0.70710678118654752f : 1.f;
        float S = au * av * 0.25f;
        float qy = c_YTAB[t] * 0.4f;   // QUALITY=80 -> FACTOR=0.4
        float qc = c_CTAB[t] * 0.4f;
        sAq[0][t] = __fdividef(S, qy);  sBq[0][t] = S * qy;
        sAq[1][t] = __fdividef(S, qc);  sBq[1][t] = S * qc;
    }

    const int tile = blockIdx.x;
    const int tx   = tile & 15;          // 16 tiles across (32 px each)
    const int ty   = (tile >> 4) & 31;   // 32 tiles down (16 px each)
    const int bimg = tile >> 9;

    const int qx = t & 15, qy = t >> 4;  // quad coords: 16 x 8 quads
    const int px = tx * 32 + qx * 2;
    const int py = ty * 16 + qy * 2;

    const size_t plane = (size_t)IMG_H * IMG_W;
    const float* pR = img + (size_t)bimg * 3 * plane + (size_t)py * IMG_W + px;
    const float* pG = pR + plane;
    const float* pB = pR + 2 * plane;

    float2 r0 = *(const float2*)pR;
    float2 r1 = *(const float2*)(pR + IMG_W);
    float2 g0 = *(const float2*)pG;
    float2 g1 = *(const float2*)(pG + IMG_W);
    float2 b0 = *(const float2*)pB;
    float2 b1 = *(const float2*)(pB + IMG_W);

    float Rq[2][2] = {{r0.x, r0.y}, {r1.x, r1.y}};
    float Gq[2][2] = {{g0.x, g0.y}, {g1.x, g1.y}};
    float Bq[2][2] = {{b0.x, b0.y}, {b1.x, b1.y}};

    float cbs = 0.f, crs = 0.f;
    #pragma unroll
    for (int dr = 0; dr < 2; dr++) {
        #pragma unroll
        for (int dc = 0; dc < 2; dc++) {
            float r = Rq[dr][dc] * 255.f;
            float g = Gq[dr][dc] * 255.f;
            float b = Bq[dr][dc] * 255.f;
            float y = 0.299f * r + 0.587f * g + 0.114f * b - 128.f;  // -128 folded
            cbs += -0.168736f * r - 0.331264f * g + 0.5f      * b;   // shifts cancel
            crs +=  0.5f      * r - 0.418688f * g - 0.081312f * b;
            int prow = qy * 2 + dr, pcol = qx * 2 + dc;
            int blk = ((prow >> 3) << 2) + (pcol >> 3);   // 4 across x 2 down
            s1[blk][prow & 7][pcol & 7] = y;
        }
    }
    s1[8  + (qx >> 3)][qy][qx & 7] = cbs * 0.25f;
    s1[10 + (qx >> 3)][qy][qx & 7] = crs * 0.25f;
    __syncthreads();

    // ---- Stage A: 1-D DCT along x: s2[b][u][j] = sum_x CT[x][u]*s1[b][x][j]
    if (t < 96) {
        int blk = t >> 3, j = t & 7;
        float in[8], a[8];
        #pragma unroll
        for (int x = 0; x < 8; x++) in[x] = s1[blk][x][j];
        dct8_fwd(in, a);
        #pragma unroll
        for (int u = 0; u < 8; u++) s2[blk][u][j] = a[u];
    }
    __syncthreads();

    // ---- Stage B: DCT along y, diff_round quant, IDCT along y.
    if (t < 96) {
        int blk = t >> 3, u = t & 7;
        int ti = (blk < 8) ? 0 : 1;
        float row[8], cv[8];
        #pragma unroll
        for (int y = 0; y < 8; y++) row[y] = s2[blk][u][y];
        dct8_fwd(row, cv);

        const float4 qa0 = *(const float4*)&sAq[ti][u * 8];
        const float4 qa1 = *(const float4*)&sAq[ti][u * 8 + 4];
        const float4 qb0 = *(const float4*)&sBq[ti][u * 8];
        const float4 qb1 = *(const float4*)&sBq[ti][u * 8 + 4];
        const float Aq[8]  = {qa0.x, qa0.y, qa0.z, qa0.w, qa1.x, qa1.y, qa1.z, qa1.w};
        const float Bq2[8] = {qb0.x, qb0.y, qb0.z, qb0.w, qb1.x, qb1.y, qb1.z, qb1.w};

        float h[8];
        #pragma unroll
        for (int v = 0; v < 8; v++) {
            float c = cv[v] * Aq[v];
            float r = rintf(c);               // round-half-even == jnp.round
            float d = c - r;
            h[v] = (r + d * d * d) * Bq2[v];
        }
        float p[8];
        dct8_inv(h, p);
        #pragma unroll
        for (int y = 0; y < 8; y++) s1[blk][u][y] = p[y];
    }
    __syncthreads();

    // ---- Stage C: IDCT along x: s2[b][x][j] = sum_u CT[x][u]*s1[b][u][j]
    if (t < 96) {
        int blk = t >> 3, j = t & 7;
        float in[8], p[8];
        #pragma unroll
        for (int u = 0; u < 8; u++) in[u] = s1[blk][u][j];
        dct8_inv(in, p);
        float add = (blk < 8) ? 128.f : 0.f;   // chroma +128/-128 cancels
        #pragma unroll
        for (int x = 0; x < 8; x++) s2[blk][x][j] = p[x] + add;
    }
    __syncthreads();

    // ---- Writeback: upsample chroma, YCbCr->RGB, clip.
    float cb = s2[8  + (qx >> 3)][qy][qx & 7];
    float cr = s2[10 + (qx >> 3)][qy][qx & 7];

    float* qR = out + (size_t)bimg * 3 * plane + (size_t)py * IMG_W + px;
    float* qG = qR + plane;
    float* qB = qR + 2 * plane;

    #pragma unroll
    for (int dr = 0; dr < 2; dr++) {
        float2 ro, go, bo;
        #pragma unroll
        for (int dc = 0; dc < 2; dc++) {
            int prow = qy * 2 + dr, pcol = qx * 2 + dc;
            int blk = ((prow >> 3) << 2) + (pcol >> 3);
            float y = s2[blk][prow & 7][pcol & 7];
            float Rv = y + 1.402f * cr;
            float Gv = y - 0.344136f * cb - 0.714136f * cr;
            float Bv = y + 1.772f * cb;
            Rv = fminf(fmaxf(Rv, 0.f), 255.f) * (1.f / 255.f);
            Gv = fminf(fmaxf(Gv, 0.f), 255.f) * (1.f / 255.f);
            Bv = fminf(fmaxf(Bv, 0.f), 255.f) * (1.f / 255.f);
            if (dc == 0) { ro.x = Rv; go.x = Gv; bo.x = Bv; }
            else         { ro.y = Rv; go.y = Gv; bo.y = Bv; }
        }
        *(float2*)(qR + dr * IMG_W) = ro;
        *(float2*)(qG + dr * IMG_W) = go;
        *(float2*)(qB + dr * IMG_W) = bo;
    }
}

extern "C" void kernel_launch(void* const* d_in, const int* in_sizes, int n_in,
                              void* d_out, int out_size) {
    const float* img = (const float*)d_in[0];
    float* out = (float*)d_out;
    int batch = in_sizes[0] / (3 * IMG_H * IMG_W);             // 32
    int tiles = batch * (IMG_H / 16) * (IMG_W / 32);           // 16384
    jpeg_tile_kernel<<<tiles, 128>>>(img, out);
}